// round 14
// baseline (speedup 1.0000x reference)
#include <cuda_runtime.h>
#include <cuda_bf16.h>
#include <math.h>
#include <stdint.h>

#define D_MODEL 512
#define NH      8
#define DK      64
#define BATCH   4
#define SEQ     2048
#define MTOT    (BATCH * SEQ)   // 8192
#define NWORDS  (SEQ / 32)      // 64 mask words per row
#define IN_SZ   ((size_t)MTOT * D_MODEL)     // 4194304
#define W_SZ    ((size_t)D_MODEL * D_MODEL)  // 262144

// Scratch (allocation-free rule: __device__ globals)
__device__ float g_Qh[IN_SZ];
__device__ __align__(16) uint16_t g_Inhi[3 * IN_SZ];
__device__ __align__(16) uint16_t g_Inlo[3 * IN_SZ];
__device__ __align__(16) uint16_t g_Whi[4 * W_SZ];
__device__ __align__(16) uint16_t g_Wlo[4 * W_SZ];
__device__ __align__(16) uint16_t g_Khi[IN_SZ];   // f16 hi/lo
__device__ __align__(16) uint16_t g_Klo[IN_SZ];
__device__ __align__(16) uint16_t g_Vhi[IN_SZ];   // f16 hi/lo
__device__ __align__(16) uint16_t g_Vlo[IN_SZ];
__device__ __align__(16) uint16_t g_Ohi[IN_SZ];   // bf16 hi/lo (O-proj operand)
__device__ __align__(16) uint16_t g_Olo[IN_SZ];
__device__ __align__(16) unsigned g_Mb[(size_t)SEQ * NWORDS];

// ---------------------------------------------------------------------------
// bf16 helpers
// ---------------------------------------------------------------------------
__device__ __forceinline__ unsigned pack2(float e0, float e1) {
    unsigned r;
    asm("cvt.rn.bf16x2.f32 %0, %1, %2;" : "=r"(r) : "f"(e1), "f"(e0));
    return r;
}
__device__ __forceinline__ void split2(float x0, float x1,
                                       unsigned& hi, unsigned& lo) {
    hi = pack2(x0, x1);
    float h0 = __uint_as_float(hi << 16);
    float h1 = __uint_as_float(hi & 0xffff0000u);
    lo = pack2(x0 - h0, x1 - h1);
}

// ---------------------------------------------------------------------------
// f16 helpers
// ---------------------------------------------------------------------------
__device__ __forceinline__ unsigned pack2h(float e0, float e1) {
    unsigned r;
    asm("cvt.rn.f16x2.f32 %0, %1, %2;" : "=r"(r) : "f"(e1), "f"(e0));
    return r;
}
__device__ __forceinline__ void split2h(float x0, float x1,
                                        unsigned& hi, unsigned& lo) {
    hi = pack2h(x0, x1);
    float h0, h1;
    asm("{.reg .f16 a,b;\n\t mov.b32 {a,b}, %2;\n\t"
        "cvt.f32.f16 %0, a;\n\t cvt.f32.f16 %1, b;}"
        : "=f"(h0), "=f"(h1) : "r"(hi));
    lo = pack2h(x0 - h0, x1 - h1);
}
__device__ __forceinline__ unsigned ex2h2(unsigned d) {
    unsigned r;
    asm("ex2.approx.f16x2 %0, %1;" : "=r"(r) : "r"(d));
    return r;
}

// m16n8k16 MMAs, D += A*B
__device__ __forceinline__ void mma_bf16(float c[4], const unsigned a[4],
                                         unsigned b0, unsigned b1) {
    asm("mma.sync.aligned.m16n8k16.row.col.f32.bf16.bf16.f32 "
        "{%0,%1,%2,%3}, {%4,%5,%6,%7}, {%8,%9}, {%0,%1,%2,%3};"
        : "+f"(c[0]), "+f"(c[1]), "+f"(c[2]), "+f"(c[3])
        : "r"(a[0]), "r"(a[1]), "r"(a[2]), "r"(a[3]), "r"(b0), "r"(b1));
}
__device__ __forceinline__ void mma_f16(float c[4], const unsigned a[4],
                                        unsigned b0, unsigned b1) {
    asm("mma.sync.aligned.m16n8k16.row.col.f32.f16.f16.f32 "
        "{%0,%1,%2,%3}, {%4,%5,%6,%7}, {%8,%9}, {%0,%1,%2,%3};"
        : "+f"(c[0]), "+f"(c[1]), "+f"(c[2]), "+f"(c[3])
        : "r"(a[0]), "r"(a[1]), "r"(a[2]), "r"(a[3]), "r"(b0), "r"(b1));
}

__device__ __forceinline__ void ldsm_x4(unsigned& r0, unsigned& r1,
                                        unsigned& r2, unsigned& r3,
                                        unsigned addr) {
    asm volatile("ldmatrix.sync.aligned.m8n8.x4.shared.b16 {%0,%1,%2,%3}, [%4];"
                 : "=r"(r0), "=r"(r1), "=r"(r2), "=r"(r3) : "r"(addr));
}
__device__ __forceinline__ void ldsm_x4_t(unsigned& r0, unsigned& r1,
                                          unsigned& r2, unsigned& r3,
                                          unsigned addr) {
    asm volatile("ldmatrix.sync.aligned.m8n8.x4.trans.shared.b16 {%0,%1,%2,%3}, [%4];"
                 : "=r"(r0), "=r"(r1), "=r"(r2), "=r"(r3) : "r"(addr));
}

// cp.async helpers
__device__ __forceinline__ void cp16(unsigned saddr, const void* g) {
    asm volatile("cp.async.cg.shared.global [%0], [%1], 16;"
                 :: "r"(saddr), "l"(g));
}
__device__ __forceinline__ void cp8(unsigned saddr, const void* g) {
    asm volatile("cp.async.ca.shared.global [%0], [%1], 8;"
                 :: "r"(saddr), "l"(g));
}
__device__ __forceinline__ void cp_commit() {
    asm volatile("cp.async.commit_group;");
}
template<int N> __device__ __forceinline__ void cp_wait() {
    asm volatile("cp.async.wait_group %0;" :: "n"(N));
}

// ---------------------------------------------------------------------------
// Prep kernels
// ---------------------------------------------------------------------------
__global__ __launch_bounds__(256)
void mask_bits_kernel(const int* __restrict__ mask)
{
    int w = blockIdx.x * 256 + threadIdx.x;
    const int* mp = mask + (size_t)w * 32;
    unsigned bits = 0;
#pragma unroll
    for (int j = 0; j < 8; j++) {
        int4 m = *(const int4*)(mp + 4 * j);
        bits |= (unsigned)(m.x != 0) << (4 * j);
        bits |= (unsigned)(m.y != 0) << (4 * j + 1);
        bits |= (unsigned)(m.z != 0) << (4 * j + 2);
        bits |= (unsigned)(m.w != 0) << (4 * j + 3);
    }
    g_Mb[w] = bits;
}

__global__ __launch_bounds__(256)
void split_in_kernel(const float* __restrict__ q,
                     const float* __restrict__ k,
                     const float* __restrict__ v)
{
    int which = blockIdx.y;
    const float* src = (which == 0) ? q : (which == 1) ? k : v;
    size_t i = ((size_t)blockIdx.x * 256 + threadIdx.x) * 4;
    float4 x = *(const float4*)(src + i);
    unsigned h01, l01, h23, l23;
    split2(x.x, x.y, h01, l01);
    split2(x.z, x.w, h23, l23);
    size_t o = (size_t)which * IN_SZ + i;
    *(uint2*)&g_Inhi[o] = make_uint2(h01, h23);
    *(uint2*)&g_Inlo[o] = make_uint2(l01, l23);
}

__global__ __launch_bounds__(256)
void split_w_kernel(const float* __restrict__ w0,
                    const float* __restrict__ w1,
                    const float* __restrict__ w2,
                    const float* __restrict__ w3)
{
    int which = blockIdx.y;
    const float* src = (which == 0) ? w0 : (which == 1) ? w1
                     : (which == 2) ? w2 : w3;
    size_t i = ((size_t)blockIdx.x * 256 + threadIdx.x) * 4;
    float4 x = *(const float4*)(src + i);
    unsigned h01, l01, h23, l23;
    split2(x.x, x.y, h01, l01);
    split2(x.z, x.w, h23, l23);
    size_t o = (size_t)which * W_SZ + i;
    *(uint2*)&g_Whi[o] = make_uint2(h01, h23);
    *(uint2*)&g_Wlo[o] = make_uint2(l01, l23);
}

// ---------------------------------------------------------------------------
// Projection GEMM: 256 threads, tile 128(M) x 128(N) x 32(K-step), 8 warps.
// Warp (wm = w&1, wn = w>>1) owns 64m x 32n. Same per-warp code as before.
// mode 0: f32 [M,512]; mode 1: f32 head layout; mode 2: f16 hi/lo head layout
// ---------------------------------------------------------------------------
#define PBM  128
#define PBN  128
#define PBK  32
#define PKST 40
#define P_STG_U16   (2 * PBM * PKST + 2 * PBN * PKST)   // 20480
#define P_STG_BYTES (P_STG_U16 * 2)                      // 40960
#define PROJ_SMEM   (2 * P_STG_BYTES)                    // 81920
#define NKI  (D_MODEL / PBK)                             // 16

__device__ __forceinline__ void proj_stage(unsigned sb,
        const uint16_t* __restrict__ Ahi, const uint16_t* __restrict__ Alo,
        const uint16_t* __restrict__ Whi, const uint16_t* __restrict__ Wlo,
        int m0, int n0, int k0, int tid)
{
#pragma unroll
    for (int l = 0; l < 2; l++) {
        int v   = l * 256 + tid;           // 0..511
        int row = v >> 2, cb = v & 3;
        size_t   go = (size_t)(m0 + row) * D_MODEL + k0 + cb * 8;
        unsigned so = 2u * (row * PKST + cb * 8);
        cp16(sb + so,                     Ahi + go);
        cp16(sb + 2u * PBM * PKST + so,   Alo + go);
    }
#pragma unroll
    for (int l = 0; l < 2; l++) {
        int v   = l * 256 + tid;           // 0..511 (W has 128 rows)
        int row = v >> 2, cb = v & 3;
        size_t   go = (size_t)(n0 + row) * D_MODEL + k0 + cb * 8;
        unsigned so = 2u * (row * PKST + cb * 8);
        cp16(sb + 4u * PBM * PKST + so,                     Whi + go);
        cp16(sb + 4u * PBM * PKST + 2u * PBN * PKST + so,   Wlo + go);
    }
    cp_commit();
}

__global__ __launch_bounds__(256)
void proj_kernel(const uint16_t* __restrict__ Ahi,
                 const uint16_t* __restrict__ Alo,
                 const uint16_t* __restrict__ Whi,
                 const uint16_t* __restrict__ Wlo,
                 const float* __restrict__ bias,
                 float* __restrict__ Yf,
                 uint16_t* __restrict__ Yhi,
                 uint16_t* __restrict__ Ylo,
                 int mode)
{
    extern __shared__ char psm[];
    const unsigned sbase = (unsigned)__cvta_generic_to_shared(psm);

    const int tid  = threadIdx.x;
    const int lane = tid & 31;
    const int w    = tid >> 5;       // 0..7
    const int wm   = w & 1;          // m 64-half
    const int wn   = w >> 1;         // n 32-quarter (0..3)
    const int g    = lane >> 2;
    const int t    = lane & 3;
    const int m0   = blockIdx.y * PBM;
    const int n0   = blockIdx.x * PBN;

    float c[4][4][4];
#pragma unroll
    for (int i = 0; i < 4; i++)
#pragma unroll
        for (int j = 0; j < 4; j++)
#pragma unroll
            for (int q = 0; q < 4; q++) c[i][j][q] = 0.f;

    const unsigned a_lane = (wm * 64 + ((lane >> 3) & 1) * 8 + (lane & 7)) * PKST
                          + (lane >> 4) * 8;
    const unsigned b_lane = (wn * 32 + (lane & 7)) * PKST
                          + ((lane >> 3) & 1) * 8
                          + (lane >> 4) * (PBN * PKST);
    const unsigned a_hi_off = 2 * a_lane;
    const unsigned a_lo_off = a_hi_off + 2 * (PBM * PKST);
    const unsigned b_off    = 4 * PBM * PKST + 2 * b_lane;

    proj_stage(sbase, Ahi, Alo, Whi, Wlo, m0, n0, 0, tid);

    for (int ki = 0; ki < NKI; ki++) {
        const int st = ki & 1;
        __syncthreads();
        if (ki + 1 < NKI) {
            proj_stage(sbase + (st ^ 1) * P_STG_BYTES,
                       Ahi, Alo, Whi, Wlo, m0, n0, (ki + 1) * PBK, tid);
            cp_wait<1>();
        } else {
            cp_wait<0>();
        }
        __syncthreads();

        const unsigned sb = sbase + st * P_STG_BYTES;
#pragma unroll
        for (int kk = 0; kk < 2; kk++) {
            unsigned ah[4][4], al[4][4];
#pragma unroll
            for (int mt = 0; mt < 4; mt++) {
                unsigned off = 2 * (mt * 16 * PKST + kk * 16);
                ldsm_x4(ah[mt][0], ah[mt][1], ah[mt][2], ah[mt][3],
                        sb + a_hi_off + off);
                ldsm_x4(al[mt][0], al[mt][1], al[mt][2], al[mt][3],
                        sb + a_lo_off + off);
            }
#pragma unroll
            for (int nt = 0; nt < 4; nt++) {
                unsigned bh0, bh1, bl0, bl1;
                ldsm_x4(bh0, bh1, bl0, bl1,
                        sb + b_off + 2 * (nt * 8 * PKST + kk * 16));
#pragma unroll
                for (int mt = 0; mt < 4; mt++) {
                    mma_bf16(c[mt][nt], al[mt], bh0, bh1);
                    mma_bf16(c[mt][nt], ah[mt], bl0, bl1);
                    mma_bf16(c[mt][nt], ah[mt], bh0, bh1);
                }
            }
        }
    }

    // ---- epilogue ----
#pragma unroll
    for (int mt = 0; mt < 4; mt++) {
#pragma unroll
        for (int nt = 0; nt < 4; nt++) {
            int n = n0 + wn * 32 + nt * 8 + t * 2;
            float2 bi = *(const float2*)(bias + n);
#pragma unroll
            for (int half = 0; half < 2; half++) {
                int m = m0 + wm * 64 + mt * 16 + g + half * 8;
                float2 val = make_float2(c[mt][nt][half * 2]     + bi.x,
                                         c[mt][nt][half * 2 + 1] + bi.y);
                if (mode == 0) {
                    *(float2*)&Yf[(size_t)m * D_MODEL + n] = val;
                } else {
                    int bb = m >> 11;
                    int s  = m & (SEQ - 1);
                    int hh = n >> 6;
                    int d  = n & (DK - 1);
                    size_t idx = (((size_t)(bb * NH + hh) * SEQ) + s) * DK + d;
                    if (mode == 1) {
                        *(float2*)&Yf[idx] = val;
                    } else {
                        unsigned hi, lo;
                        split2h(val.x, val.y, hi, lo);
                        *(unsigned*)&Yhi[idx] = hi;
                        *(unsigned*)&Ylo[idx] = lo;
                    }
                }
            }
        }
    }
}

// ---------------------------------------------------------------------------
// Flash attention: 256 threads, BQ=128 (8 warps x 16 q rows), key tiles 64.
// f16 path: QK 3-term; softmax via ex2.approx.f16x2; PV 2-term; ones-MMA lsum.
// ---------------------------------------------------------------------------
#define BQ    128
#define BKT   64
#define NT_T  (SEQ / BKT)          // 32 tiles
#define KST   72
#define MAT_U16   (64 * KST)       // 4608
#define MAT_BYTES (MAT_U16 * 2)    // 9216
#define STG_BYTES (4 * MAT_BYTES)  // 36864
#define MS_OFF_BYTES (2 * STG_BYTES)
#define ATTN_SMEM (MS_OFF_BYTES + 2 * BQ * 8)    // 75776
#define ONES_H2  0x3C003C00u       // f16x2 {1.0, 1.0}
#define SC2      0.18033688f       // 0.125 * log2(e)

__device__ __forceinline__ void stage_tile(unsigned smem_u32, int st,
                                           size_t bh, int qbase, int tile,
                                           int tid)
{
    const int k0 = tile * BKT;
    const unsigned sb = smem_u32 + st * STG_BYTES;
#pragma unroll
    for (int l = 0; l < 2; l++) {
        int cc  = tid + l * 256;           // 0..511
        int row = cc >> 3;
        int col = cc & 7;
        size_t  go = (size_t)(bh + k0 + row) * DK + col * 8;
        unsigned so = 2 * (row * KST + col * 8);
        cp16(sb + so,                 g_Khi + go);
        cp16(sb + MAT_BYTES + so,     g_Klo + go);
        cp16(sb + 2 * MAT_BYTES + so, g_Vhi + go);
        cp16(sb + 3 * MAT_BYTES + so, g_Vlo + go);
    }
    if (tid < BQ) {
        cp8(smem_u32 + MS_OFF_BYTES + st * (BQ * 8) + tid * 8,
            g_Mb + (size_t)(qbase + tid) * NWORDS + tile * 2);
    }
    cp_commit();
}

__global__ __launch_bounds__(256)
void attn_kernel()
{
    extern __shared__ char dsm[];
    const unsigned smem_u32 = (unsigned)__cvta_generic_to_shared(dsm);
    const unsigned* Msp = (const unsigned*)(dsm + MS_OFF_BYTES);

    const int tid  = threadIdx.x;
    const int w    = tid >> 5;       // 0..7
    const int lane = tid & 31;
    const int g    = lane >> 2;
    const int t    = lane & 3;
    const int b    = blockIdx.z;
    const int h    = blockIdx.y;
    const int qbase = blockIdx.x * BQ;
    const size_t bh = ((size_t)b * NH + h) * SEQ;

    stage_tile(smem_u32, 0, bh, qbase, 0, tid);

    // ---- Q fragments (f16 hi/lo) once ----
    unsigned ah[4][4], al[4][4];
    {
        const float* q0p = g_Qh + (bh + qbase + w * 16 + g) * DK;
        const float* q1p = q0p + 8 * DK;
#pragma unroll
        for (int kc = 0; kc < 4; kc++) {
            int d = kc * 16 + t * 2;
            split2h(q0p[d],     q0p[d + 1], ah[kc][0], al[kc][0]);
            split2h(q1p[d],     q1p[d + 1], ah[kc][1], al[kc][1]);
            split2h(q0p[d + 8], q0p[d + 9], ah[kc][2], al[kc][2]);
            split2h(q1p[d + 8], q1p[d + 9], ah[kc][3], al[kc][3]);
        }
    }

    float o[8][4];
#pragma unroll
    for (int nt = 0; nt < 8; nt++)
#pragma unroll
        for (int i = 0; i < 4; i++) o[nt][i] = 0.f;
    float osum[4] = {0.f, 0.f, 0.f, 0.f};
    float mrow0 = -1e30f, mrow1 = -1e30f;

    const unsigned k_lane = (lane & 7) * KST + ((lane >> 3) & 1) * 8
                          + (lane >> 4) * MAT_U16;
    const unsigned v_lane = ((lane & 7) + ((lane >> 3) & 1) * 8) * KST
                          + (lane >> 4) * MAT_U16;
    const unsigned k_ad = smem_u32 + 2 * k_lane;
    const unsigned v_ad = smem_u32 + 2 * MAT_BYTES + 2 * v_lane;

    for (int tile = 0; tile < NT_T; tile++) {
        const int st = tile & 1;
        __syncthreads();
        if (tile + 1 < NT_T) {
            stage_tile(smem_u32, st ^ 1, bh, qbase, tile + 1, tid);
            cp_wait<1>();
        } else {
            cp_wait<0>();
        }
        __syncthreads();

        const unsigned kst_ad = k_ad + st * STG_BYTES;
        const unsigned vst_ad = v_ad + st * STG_BYTES;

        // ---- S = Q @ K^T (3-term f16) ----
        float s[8][4];
#pragma unroll
        for (int nt = 0; nt < 8; nt++) {
            float c[4] = {0.f, 0.f, 0.f, 0.f};
#pragma unroll
            for (int kc = 0; kc < 4; kc++) {
                unsigned bh0, bh1, bl0, bl1;
                ldsm_x4(bh0, bh1, bl0, bl1,
                        kst_ad + 2 * (nt * 8 * KST + kc * 16));
                mma_f16(c, al[kc], bh0, bh1);
                mma_f16(c, ah[kc], bl0, bl1);
                mma_f16(c, ah[kc], bh0, bh1);
            }
            s[nt][0] = c[0]; s[nt][1] = c[1]; s[nt][2] = c[2]; s[nt][3] = c[3];
        }

        // ---- mask + scale (log2 domain) + online softmax ----
        unsigned pf[8][2];
        {
            int row0 = w * 16 + g;
            const unsigned* ms = Msp + st * (BQ * 2);
            unsigned long long M0 = (unsigned long long)ms[row0 * 2]
                                  | ((unsigned long long)ms[row0 * 2 + 1] << 32);
            unsigned long long M1 = (unsigned long long)ms[(row0 + 8) * 2]
                                  | ((unsigned long long)ms[(row0 + 8) * 2 + 1] << 32);
            float rmax0 = -1e30f, rmax1 = -1e30f;
#pragma unroll
            for (int nt = 0; nt < 8; nt++) {
                unsigned sh = nt * 8 + t * 2;
                unsigned b0 = (unsigned)(M0 >> sh);
                unsigned b1 = (unsigned)(M1 >> sh);
                s[nt][0] = (b0 & 1u) ? s[nt][0] * SC2 : -1e9f;
                s[nt][1] = (b0 & 2u) ? s[nt][1] * SC2 : -1e9f;
                s[nt][2] = (b1 & 1u) ? s[nt][2] * SC2 : -1e9f;
                s[nt][3] = (b1 & 2u) ? s[nt][3] * SC2 : -1e9f;
                rmax0 = fmaxf(rmax0, fmaxf(s[nt][0], s[nt][1]));
                rmax1 = fmaxf(rmax1, fmaxf(s[nt][2], s[nt][3]));
            }
            rmax0 = fmaxf(rmax0, __shfl_xor_sync(0xffffffffu, rmax0, 1));
            rmax0 = fmaxf(rmax0, __shfl_xor_sync(0xffffffffu, rmax0, 2));
            rmax1 = fmaxf(rmax1, __shfl_xor_sync(0xffffffffu, rmax1, 1));
            rmax1 = fmaxf(rmax1, __shfl_xor_sync(0xffffffffu, rmax1, 2));

            float mnew0 = fmaxf(mrow0, rmax0);
            float mnew1 = fmaxf(mrow1, rmax1);
            float corr0 = exp2f(mrow0 - mnew0);
            float corr1 = exp2f(mrow1 - mnew1);
            mrow0 = mnew0; mrow1 = mnew1;

#pragma unroll
            for (int nt = 0; nt < 8; nt++) {
                pf[nt][0] = ex2h2(pack2h(s[nt][0] - mnew0, s[nt][1] - mnew0));
                pf[nt][1] = ex2h2(pack2h(s[nt][2] - mnew1, s[nt][3] - mnew1));
            }

#pragma unroll
            for (int nt = 0; nt < 8; nt++) {
                o[nt][0] *= corr0; o[nt][1] *= corr0;
                o[nt][2] *= corr1; o[nt][3] *= corr1;
            }
            osum[0] *= corr0; osum[1] *= corr0;
            osum[2] *= corr1; osum[3] *= corr1;
        }

        // ---- O += P @ V ; lsum via ones-column MMA ----
#pragma unroll
        for (int kc = 0; kc < 4; kc++) {
            unsigned a[4] = { pf[2 * kc][0],     pf[2 * kc][1],
                              pf[2 * kc + 1][0], pf[2 * kc + 1][1] };
            mma_f16(osum, a, ONES_H2, ONES_H2);
#pragma unroll
            for (int nt = 0; nt < 8; nt++) {
                unsigned vh0, vh1, vl0, vl1;
                ldsm_x4_t(vh0, vh1, vl0, vl1,
                          vst_ad + 2 * (kc * 16 * KST + nt * 8));
                mma_f16(o[nt], a, vh0, vh1);
                mma_f16(o[nt], a, vl0, vl1);
            }
        }
    }

    // ---- epilogue: normalize, split (bf16 for O-proj), write ----
    float inv0 = 1.0f / osum[0];
    float inv1 = 1.0f / osum[2];
    int q0 = qbase + w * 16 + g;
    size_t base0 = ((size_t)b * SEQ + q0) * D_MODEL + h * DK;
    size_t base1 = base0 + 8 * (size_t)D_MODEL;
#pragma unroll
    for (int nt = 0; nt < 8; nt++) {
        unsigned hi, lo;
        split2(o[nt][0] * inv0, o[nt][1] * inv0, hi, lo);
        *(unsigned*)&g_Ohi[base0 + nt * 8 + t * 2] = hi;
        *(unsigned*)&g_Olo[base0 + nt * 8 + t * 2] = lo;
        split2(o[nt][2] * inv1, o[nt][3] * inv1, hi, lo);
        *(unsigned*)&g_Ohi[base1 + nt * 8 + t * 2] = hi;
        *(unsigned*)&g_Olo[base1 + nt * 8 + t * 2] = lo;
    }
}

// ---------------------------------------------------------------------------

extern "C" void kernel_launch(void* const* d_in, const int* in_sizes, int n_in,
                              void* d_out, int out_size)
{
    (void)in_sizes; (void)n_in; (void)out_size;
    const float* q    = (const float*)d_in[0];
    const float* k    = (const float*)d_in[1];
    const float* v    = (const float*)d_in[2];
    const int*   mask = (const int*)  d_in[3];
    const float* Wq   = (const float*)d_in[4];
    const float* bq   = (const float*)d_in[5];
    const float* Wk   = (const float*)d_in[6];
    const float* bk   = (const float*)d_in[7];
    const float* Wv   = (const float*)d_in[8];
    const float* bv   = (const float*)d_in[9];
    const float* Wo   = (const float*)d_in[10];
    const float* bo   = (const float*)d_in[11];
    float* out = (float*)d_out;

    float *Qh;
    uint16_t *Inhi, *Inlo, *Whi, *Wlo, *Khi, *Klo, *Vhi, *Vlo, *Ohi, *Olo;
    cudaGetSymbolAddress((void**)&Qh,   g_Qh);
    cudaGetSymbolAddress((void**)&Inhi, g_Inhi);
    cudaGetSymbolAddress((void**)&Inlo, g_Inlo);
    cudaGetSymbolAddress((void**)&Whi,  g_Whi);
    cudaGetSymbolAddress((void**)&Wlo,  g_Wlo);
    cudaGetSymbolAddress((void**)&Khi,  g_Khi);
    cudaGetSymbolAddress((void**)&Klo,  g_Klo);
    cudaGetSymbolAddress((void**)&Vhi,  g_Vhi);
    cudaGetSymbolAddress((void**)&Vlo,  g_Vlo);
    cudaGetSymbolAddress((void**)&Ohi,  g_Ohi);
    cudaGetSymbolAddress((void**)&Olo,  g_Olo);

    cudaFuncSetAttribute(attn_kernel,
                         cudaFuncAttributeMaxDynamicSharedMemorySize,
                         ATTN_SMEM);
    cudaFuncSetAttribute(proj_kernel,
                         cudaFuncAttributeMaxDynamicSharedMemorySize,
                         PROJ_SMEM);

    mask_bits_kernel<<<SEQ * NWORDS / 256, 256>>>(mask);
    split_in_kernel<<<dim3(IN_SZ / 1024, 3), 256>>>(q, k, v);
    split_w_kernel<<<dim3(W_SZ / 1024, 4), 256>>>(Wq, Wk, Wv, Wo);

    dim3 proj_grid(D_MODEL / PBN, MTOT / PBM);   // (4, 64)
    proj_kernel<<<proj_grid, 256, PROJ_SMEM>>>(
        Inhi, Inlo, Whi, Wlo, bq, Qh, nullptr, nullptr, 1);
    proj_kernel<<<proj_grid, 256, PROJ_SMEM>>>(
        Inhi + IN_SZ, Inlo + IN_SZ, Whi + W_SZ, Wlo + W_SZ,
        bk, nullptr, Khi, Klo, 2);
    proj_kernel<<<proj_grid, 256, PROJ_SMEM>>>(
        Inhi + 2 * IN_SZ, Inlo + 2 * IN_SZ, Whi + 2 * W_SZ, Wlo + 2 * W_SZ,
        bv, nullptr, Vhi, Vlo, 2);

    dim3 attn_grid(SEQ / BQ, NH, BATCH);         // (16, 8, 4)
    attn_kernel<<<attn_grid, 256, ATTN_SMEM>>>();

    proj_kernel<<<proj_grid, 256, PROJ_SMEM>>>(
        Ohi, Olo, Whi + 3 * W_SZ, Wlo + 3 * W_SZ, bo, out, nullptr, nullptr, 0);
}

// round 16
// speedup vs baseline: 1.2378x; 1.2378x over previous
#include <cuda_runtime.h>
#include <cuda_bf16.h>
#include <math.h>
#include <stdint.h>

#define D_MODEL 512
#define NH      8
#define DK      64
#define BATCH   4
#define SEQ     2048
#define MTOT    (BATCH * SEQ)   // 8192
#define NWORDS  (SEQ / 32)      // 64 mask words per row
#define IN_SZ   ((size_t)MTOT * D_MODEL)     // 4194304
#define W_SZ    ((size_t)D_MODEL * D_MODEL)  // 262144

// Scratch (allocation-free rule: __device__ globals)
__device__ float g_Qh[IN_SZ];
__device__ __align__(16) uint16_t g_Inhi[3 * IN_SZ];
__device__ __align__(16) uint16_t g_Inlo[3 * IN_SZ];
__device__ __align__(16) uint16_t g_Whi[4 * W_SZ];
__device__ __align__(16) uint16_t g_Wlo[4 * W_SZ];
__device__ __align__(16) uint16_t g_Khi[IN_SZ];   // f16 hi/lo
__device__ __align__(16) uint16_t g_Klo[IN_SZ];
__device__ __align__(16) uint16_t g_Vhi[IN_SZ];   // f16 (single precision term)
__device__ __align__(16) uint16_t g_Ohi[IN_SZ];   // bf16 hi/lo (O-proj operand)
__device__ __align__(16) uint16_t g_Olo[IN_SZ];
__device__ __align__(16) unsigned g_Mb[(size_t)SEQ * NWORDS];

// ---------------------------------------------------------------------------
// bf16 helpers
// ---------------------------------------------------------------------------
__device__ __forceinline__ unsigned pack2(float e0, float e1) {
    unsigned r;
    asm("cvt.rn.bf16x2.f32 %0, %1, %2;" : "=r"(r) : "f"(e1), "f"(e0));
    return r;
}
__device__ __forceinline__ void split2(float x0, float x1,
                                       unsigned& hi, unsigned& lo) {
    hi = pack2(x0, x1);
    float h0 = __uint_as_float(hi << 16);
    float h1 = __uint_as_float(hi & 0xffff0000u);
    lo = pack2(x0 - h0, x1 - h1);
}

// ---------------------------------------------------------------------------
// f16 helpers
// ---------------------------------------------------------------------------
__device__ __forceinline__ unsigned pack2h(float e0, float e1) {
    unsigned r;
    asm("cvt.rn.f16x2.f32 %0, %1, %2;" : "=r"(r) : "f"(e1), "f"(e0));
    return r;
}
__device__ __forceinline__ void split2h(float x0, float x1,
                                        unsigned& hi, unsigned& lo) {
    hi = pack2h(x0, x1);
    float h0, h1;
    asm("{.reg .f16 a,b;\n\t mov.b32 {a,b}, %2;\n\t"
        "cvt.f32.f16 %0, a;\n\t cvt.f32.f16 %1, b;}"
        : "=f"(h0), "=f"(h1) : "r"(hi));
    lo = pack2h(x0 - h0, x1 - h1);
}
__device__ __forceinline__ unsigned ex2h2(unsigned d) {
    unsigned r;
    asm("ex2.approx.f16x2 %0, %1;" : "=r"(r) : "r"(d));
    return r;
}

// m16n8k16 MMAs, D += A*B
__device__ __forceinline__ void mma_bf16(float c[4], const unsigned a[4],
                                         unsigned b0, unsigned b1) {
    asm("mma.sync.aligned.m16n8k16.row.col.f32.bf16.bf16.f32 "
        "{%0,%1,%2,%3}, {%4,%5,%6,%7}, {%8,%9}, {%0,%1,%2,%3};"
        : "+f"(c[0]), "+f"(c[1]), "+f"(c[2]), "+f"(c[3])
        : "r"(a[0]), "r"(a[1]), "r"(a[2]), "r"(a[3]), "r"(b0), "r"(b1));
}
__device__ __forceinline__ void mma_f16(float c[4], const unsigned a[4],
                                        unsigned b0, unsigned b1) {
    asm("mma.sync.aligned.m16n8k16.row.col.f32.f16.f16.f32 "
        "{%0,%1,%2,%3}, {%4,%5,%6,%7}, {%8,%9}, {%0,%1,%2,%3};"
        : "+f"(c[0]), "+f"(c[1]), "+f"(c[2]), "+f"(c[3])
        : "r"(a[0]), "r"(a[1]), "r"(a[2]), "r"(a[3]), "r"(b0), "r"(b1));
}

__device__ __forceinline__ void ldsm_x4(unsigned& r0, unsigned& r1,
                                        unsigned& r2, unsigned& r3,
                                        unsigned addr) {
    asm volatile("ldmatrix.sync.aligned.m8n8.x4.shared.b16 {%0,%1,%2,%3}, [%4];"
                 : "=r"(r0), "=r"(r1), "=r"(r2), "=r"(r3) : "r"(addr));
}
__device__ __forceinline__ void ldsm_x4_t(unsigned& r0, unsigned& r1,
                                          unsigned& r2, unsigned& r3,
                                          unsigned addr) {
    asm volatile("ldmatrix.sync.aligned.m8n8.x4.trans.shared.b16 {%0,%1,%2,%3}, [%4];"
                 : "=r"(r0), "=r"(r1), "=r"(r2), "=r"(r3) : "r"(addr));
}

// cp.async helpers
__device__ __forceinline__ void cp16(unsigned saddr, const void* g) {
    asm volatile("cp.async.cg.shared.global [%0], [%1], 16;"
                 :: "r"(saddr), "l"(g));
}
__device__ __forceinline__ void cp8(unsigned saddr, const void* g) {
    asm volatile("cp.async.ca.shared.global [%0], [%1], 8;"
                 :: "r"(saddr), "l"(g));
}
__device__ __forceinline__ void cp_commit() {
    asm volatile("cp.async.commit_group;");
}
template<int N> __device__ __forceinline__ void cp_wait() {
    asm volatile("cp.async.wait_group %0;" :: "n"(N));
}

// ---------------------------------------------------------------------------
// Prep kernels
// ---------------------------------------------------------------------------
__global__ __launch_bounds__(256)
void mask_bits_kernel(const int* __restrict__ mask)
{
    int w = blockIdx.x * 256 + threadIdx.x;
    const int* mp = mask + (size_t)w * 32;
    unsigned bits = 0;
#pragma unroll
    for (int j = 0; j < 8; j++) {
        int4 m = *(const int4*)(mp + 4 * j);
        bits |= (unsigned)(m.x != 0) << (4 * j);
        bits |= (unsigned)(m.y != 0) << (4 * j + 1);
        bits |= (unsigned)(m.z != 0) << (4 * j + 2);
        bits |= (unsigned)(m.w != 0) << (4 * j + 3);
    }
    g_Mb[w] = bits;
}

__global__ __launch_bounds__(256)
void split_in_kernel(const float* __restrict__ q,
                     const float* __restrict__ k,
                     const float* __restrict__ v)
{
    int which = blockIdx.y;
    const float* src = (which == 0) ? q : (which == 1) ? k : v;
    size_t i = ((size_t)blockIdx.x * 256 + threadIdx.x) * 4;
    float4 x = *(const float4*)(src + i);
    unsigned h01, l01, h23, l23;
    split2(x.x, x.y, h01, l01);
    split2(x.z, x.w, h23, l23);
    size_t o = (size_t)which * IN_SZ + i;
    *(uint2*)&g_Inhi[o] = make_uint2(h01, h23);
    *(uint2*)&g_Inlo[o] = make_uint2(l01, l23);
}

__global__ __launch_bounds__(256)
void split_w_kernel(const float* __restrict__ w0,
                    const float* __restrict__ w1,
                    const float* __restrict__ w2,
                    const float* __restrict__ w3)
{
    int which = blockIdx.y;
    const float* src = (which == 0) ? w0 : (which == 1) ? w1
                     : (which == 2) ? w2 : w3;
    size_t i = ((size_t)blockIdx.x * 256 + threadIdx.x) * 4;
    float4 x = *(const float4*)(src + i);
    unsigned h01, l01, h23, l23;
    split2(x.x, x.y, h01, l01);
    split2(x.z, x.w, h23, l23);
    size_t o = (size_t)which * W_SZ + i;
    *(uint2*)&g_Whi[o] = make_uint2(h01, h23);
    *(uint2*)&g_Wlo[o] = make_uint2(l01, l23);
}

// ---------------------------------------------------------------------------
// Projection GEMM (R13 config): 128 threads, tile 128x64x32, 4 warps.
// mode 0: f32 [M,512]; mode 1: f32 head layout; mode 2: f16 head layout
//   mode 2 writes Yhi = RN_f16(val); Ylo (if non-null) = f16(val - hi).
// ---------------------------------------------------------------------------
#define PBM  128
#define PBN  64
#define PBK  32
#define PKST 40
#define P_STG_U16   (2 * PBM * PKST + 2 * PBN * PKST)   // 15360
#define P_STG_BYTES (P_STG_U16 * 2)                      // 30720
#define PROJ_SMEM   (2 * P_STG_BYTES)                    // 61440
#define NKI  (D_MODEL / PBK)                             // 16

__device__ __forceinline__ void proj_stage(unsigned sb,
        const uint16_t* __restrict__ Ahi, const uint16_t* __restrict__ Alo,
        const uint16_t* __restrict__ Whi, const uint16_t* __restrict__ Wlo,
        int m0, int n0, int k0, int tid)
{
#pragma unroll
    for (int l = 0; l < 4; l++) {
        int v   = l * 128 + tid;
        int row = v >> 2, cb = v & 3;
        size_t   go = (size_t)(m0 + row) * D_MODEL + k0 + cb * 8;
        unsigned so = 2u * (row * PKST + cb * 8);
        cp16(sb + so,                     Ahi + go);
        cp16(sb + 2u * PBM * PKST + so,   Alo + go);
    }
#pragma unroll
    for (int l = 0; l < 2; l++) {
        int v   = l * 128 + tid;
        int row = v >> 2, cb = v & 3;
        size_t   go = (size_t)(n0 + row) * D_MODEL + k0 + cb * 8;
        unsigned so = 2u * (row * PKST + cb * 8);
        cp16(sb + 4u * PBM * PKST + so,                     Whi + go);
        cp16(sb + 4u * PBM * PKST + 2u * PBN * PKST + so,   Wlo + go);
    }
    cp_commit();
}

__global__ __launch_bounds__(128)
void proj_kernel(const uint16_t* __restrict__ Ahi,
                 const uint16_t* __restrict__ Alo,
                 const uint16_t* __restrict__ Whi,
                 const uint16_t* __restrict__ Wlo,
                 const float* __restrict__ bias,
                 float* __restrict__ Yf,
                 uint16_t* __restrict__ Yhi,
                 uint16_t* __restrict__ Ylo,
                 int mode)
{
    extern __shared__ char psm[];
    const unsigned sbase = (unsigned)__cvta_generic_to_shared(psm);

    const int tid  = threadIdx.x;
    const int lane = tid & 31;
    const int w    = tid >> 5;
    const int wm   = w & 1;
    const int wn   = w >> 1;
    const int g    = lane >> 2;
    const int t    = lane & 3;
    const int m0   = blockIdx.y * PBM;
    const int n0   = blockIdx.x * PBN;

    float c[4][4][4];
#pragma unroll
    for (int i = 0; i < 4; i++)
#pragma unroll
        for (int j = 0; j < 4; j++)
#pragma unroll
            for (int q = 0; q < 4; q++) c[i][j][q] = 0.f;

    const unsigned a_lane = (wm * 64 + ((lane >> 3) & 1) * 8 + (lane & 7)) * PKST
                          + (lane >> 4) * 8;
    const unsigned b_lane = (wn * 32 + (lane & 7)) * PKST
                          + ((lane >> 3) & 1) * 8
                          + (lane >> 4) * (PBN * PKST);
    const unsigned a_hi_off = 2 * a_lane;
    const unsigned a_lo_off = a_hi_off + 2 * (PBM * PKST);
    const unsigned b_off    = 4 * PBM * PKST + 2 * b_lane;

    proj_stage(sbase, Ahi, Alo, Whi, Wlo, m0, n0, 0, tid);

    for (int ki = 0; ki < NKI; ki++) {
        const int st = ki & 1;
        __syncthreads();
        if (ki + 1 < NKI) {
            proj_stage(sbase + (st ^ 1) * P_STG_BYTES,
                       Ahi, Alo, Whi, Wlo, m0, n0, (ki + 1) * PBK, tid);
            cp_wait<1>();
        } else {
            cp_wait<0>();
        }
        __syncthreads();

        const unsigned sb = sbase + st * P_STG_BYTES;
#pragma unroll
        for (int kk = 0; kk < 2; kk++) {
            unsigned ah[4][4], al[4][4];
#pragma unroll
            for (int mt = 0; mt < 4; mt++) {
                unsigned off = 2 * (mt * 16 * PKST + kk * 16);
                ldsm_x4(ah[mt][0], ah[mt][1], ah[mt][2], ah[mt][3],
                        sb + a_hi_off + off);
                ldsm_x4(al[mt][0], al[mt][1], al[mt][2], al[mt][3],
                        sb + a_lo_off + off);
            }
#pragma unroll
            for (int nt = 0; nt < 4; nt++) {
                unsigned bh0, bh1, bl0, bl1;
                ldsm_x4(bh0, bh1, bl0, bl1,
                        sb + b_off + 2 * (nt * 8 * PKST + kk * 16));
#pragma unroll
                for (int mt = 0; mt < 4; mt++) {
                    mma_bf16(c[mt][nt], al[mt], bh0, bh1);
                    mma_bf16(c[mt][nt], ah[mt], bl0, bl1);
                    mma_bf16(c[mt][nt], ah[mt], bh0, bh1);
                }
            }
        }
    }

    // ---- epilogue ----
#pragma unroll
    for (int mt = 0; mt < 4; mt++) {
#pragma unroll
        for (int nt = 0; nt < 4; nt++) {
            int n = n0 + wn * 32 + nt * 8 + t * 2;
            float2 bi = *(const float2*)(bias + n);
#pragma unroll
            for (int half = 0; half < 2; half++) {
                int m = m0 + wm * 64 + mt * 16 + g + half * 8;
                float2 val = make_float2(c[mt][nt][half * 2]     + bi.x,
                                         c[mt][nt][half * 2 + 1] + bi.y);
                if (mode == 0) {
                    *(float2*)&Yf[(size_t)m * D_MODEL + n] = val;
                } else {
                    int bb = m >> 11;
                    int s  = m & (SEQ - 1);
                    int hh = n >> 6;
                    int d  = n & (DK - 1);
                    size_t idx = (((size_t)(bb * NH + hh) * SEQ) + s) * DK + d;
                    if (mode == 1) {
                        *(float2*)&Yf[idx] = val;
                    } else {
                        unsigned hi, lo;
                        split2h(val.x, val.y, hi, lo);
                        *(unsigned*)&Yhi[idx] = hi;
                        if (Ylo) *(unsigned*)&Ylo[idx] = lo;
                    }
                }
            }
        }
    }
}

// ---------------------------------------------------------------------------
// Flash attention (128 thr, BQ=64): QK 3-term f16; softmax via ex2.approx;
// PV single-term f16 (ldsm_x4_t fetches TWO 8-col blocks per load: lanes
// 16-31 offset +8 u16). lsum via ones-column MMA.
// Staging: Khi | Klo | Vhi.
// ---------------------------------------------------------------------------
#define BKT   64
#define NT_T  (SEQ / BKT)          // 32 tiles
#define KST   72
#define MAT_U16   (64 * KST)       // 4608
#define MAT_BYTES (MAT_U16 * 2)    // 9216
#define STG_BYTES (3 * MAT_BYTES)  // 27648
#define MS_OFF_BYTES (2 * STG_BYTES)
#define ATTN_SMEM (MS_OFF_BYTES + 2 * 128 * 4)   // 56320
#define ONES_H2  0x3C003C00u       // f16x2 {1.0, 1.0}
#define SC2      0.18033688f       // 0.125 * log2(e)

__device__ __forceinline__ void stage_tile(unsigned smem_u32, int st,
                                           size_t bh, int qbase, int tile,
                                           int tid)
{
    const int k0 = tile * BKT;
    const unsigned sb = smem_u32 + st * STG_BYTES;
#pragma unroll
    for (int l = 0; l < 4; l++) {
        int cc  = tid + l * 128;
        int row = cc >> 3;
        int col = cc & 7;
        size_t  go = (size_t)(bh + k0 + row) * DK + col * 8;
        unsigned so = 2 * (row * KST + col * 8);
        cp16(sb + so,                 g_Khi + go);
        cp16(sb + MAT_BYTES + so,     g_Klo + go);
        cp16(sb + 2 * MAT_BYTES + so, g_Vhi + go);
    }
    if (tid < 64) {
        cp8(smem_u32 + MS_OFF_BYTES + st * 512 + tid * 8,
            g_Mb + (size_t)(qbase + tid) * NWORDS + tile * 2);
    }
    cp_commit();
}

__global__ __launch_bounds__(128)
void attn_kernel()
{
    extern __shared__ char dsm[];
    const unsigned smem_u32 = (unsigned)__cvta_generic_to_shared(dsm);
    const unsigned* Msp = (const unsigned*)(dsm + MS_OFF_BYTES);

    const int tid  = threadIdx.x;
    const int w    = tid >> 5;
    const int lane = tid & 31;
    const int g    = lane >> 2;
    const int t    = lane & 3;
    const int b    = blockIdx.z;
    const int h    = blockIdx.y;
    const int qbase = blockIdx.x * 64;
    const size_t bh = ((size_t)b * NH + h) * SEQ;

    stage_tile(smem_u32, 0, bh, qbase, 0, tid);

    // ---- Q fragments (f16 hi/lo) once ----
    unsigned ah[4][4], al[4][4];
    {
        const float* q0p = g_Qh + (bh + qbase + w * 16 + g) * DK;
        const float* q1p = q0p + 8 * DK;
#pragma unroll
        for (int kc = 0; kc < 4; kc++) {
            int d = kc * 16 + t * 2;
            split2h(q0p[d],     q0p[d + 1], ah[kc][0], al[kc][0]);
            split2h(q1p[d],     q1p[d + 1], ah[kc][1], al[kc][1]);
            split2h(q0p[d + 8], q0p[d + 9], ah[kc][2], al[kc][2]);
            split2h(q1p[d + 8], q1p[d + 9], ah[kc][3], al[kc][3]);
        }
    }

    float o[8][4];
#pragma unroll
    for (int nt = 0; nt < 8; nt++)
#pragma unroll
        for (int i = 0; i < 4; i++) o[nt][i] = 0.f;
    float osum[4] = {0.f, 0.f, 0.f, 0.f};
    float mrow0 = -1e30f, mrow1 = -1e30f;

    const unsigned k_lane = (lane & 7) * KST + ((lane >> 3) & 1) * 8
                          + (lane >> 4) * MAT_U16;
    // V (trans x4, two 8-col blocks per load): lanes 0-15 rows 0-15 at col
    // block base; lanes 16-31 same rows at +8 u16 (next 8 columns).
    const unsigned v_lane = ((lane & 7) + ((lane >> 3) & 1) * 8) * KST
                          + (lane >> 4) * 8;
    const unsigned k_ad = smem_u32 + 2 * k_lane;
    const unsigned v_ad = smem_u32 + 2 * (2 * MAT_U16) + 2 * v_lane;

    for (int tile = 0; tile < NT_T; tile++) {
        const int st = tile & 1;
        __syncthreads();
        if (tile + 1 < NT_T) {
            stage_tile(smem_u32, st ^ 1, bh, qbase, tile + 1, tid);
            cp_wait<1>();
        } else {
            cp_wait<0>();
        }
        __syncthreads();

        const unsigned kst_ad = k_ad + st * STG_BYTES;
        const unsigned vst_ad = v_ad + st * STG_BYTES;

        // ---- S = Q @ K^T (3-term f16) ----
        float s[8][4];
#pragma unroll
        for (int nt = 0; nt < 8; nt++) {
            float c[4] = {0.f, 0.f, 0.f, 0.f};
#pragma unroll
            for (int kc = 0; kc < 4; kc++) {
                unsigned bh0, bh1, bl0, bl1;
                ldsm_x4(bh0, bh1, bl0, bl1,
                        kst_ad + 2 * (nt * 8 * KST + kc * 16));
                mma_f16(c, al[kc], bh0, bh1);
                mma_f16(c, ah[kc], bl0, bl1);
                mma_f16(c, ah[kc], bh0, bh1);
            }
            s[nt][0] = c[0]; s[nt][1] = c[1]; s[nt][2] = c[2]; s[nt][3] = c[3];
        }

        // ---- mask + scale (log2 domain) + online softmax ----
        unsigned pf[8][2];
        {
            int row0 = w * 16 + g;
            const unsigned* ms = Msp + st * 128;
            unsigned long long M0 = (unsigned long long)ms[row0 * 2]
                                  | ((unsigned long long)ms[row0 * 2 + 1] << 32);
            unsigned long long M1 = (unsigned long long)ms[(row0 + 8) * 2]
                                  | ((unsigned long long)ms[(row0 + 8) * 2 + 1] << 32);
            float rmax0 = -1e30f, rmax1 = -1e30f;
#pragma unroll
            for (int nt = 0; nt < 8; nt++) {
                unsigned sh = nt * 8 + t * 2;
                unsigned b0 = (unsigned)(M0 >> sh);
                unsigned b1 = (unsigned)(M1 >> sh);
                s[nt][0] = (b0 & 1u) ? s[nt][0] * SC2 : -1e9f;
                s[nt][1] = (b0 & 2u) ? s[nt][1] * SC2 : -1e9f;
                s[nt][2] = (b1 & 1u) ? s[nt][2] * SC2 : -1e9f;
                s[nt][3] = (b1 & 2u) ? s[nt][3] * SC2 : -1e9f;
                rmax0 = fmaxf(rmax0, fmaxf(s[nt][0], s[nt][1]));
                rmax1 = fmaxf(rmax1, fmaxf(s[nt][2], s[nt][3]));
            }
            rmax0 = fmaxf(rmax0, __shfl_xor_sync(0xffffffffu, rmax0, 1));
            rmax0 = fmaxf(rmax0, __shfl_xor_sync(0xffffffffu, rmax0, 2));
            rmax1 = fmaxf(rmax1, __shfl_xor_sync(0xffffffffu, rmax1, 1));
            rmax1 = fmaxf(rmax1, __shfl_xor_sync(0xffffffffu, rmax1, 2));

            float mnew0 = fmaxf(mrow0, rmax0);
            float mnew1 = fmaxf(mrow1, rmax1);
            float corr0 = exp2f(mrow0 - mnew0);
            float corr1 = exp2f(mrow1 - mnew1);
            mrow0 = mnew0; mrow1 = mnew1;

#pragma unroll
            for (int nt = 0; nt < 8; nt++) {
                pf[nt][0] = ex2h2(pack2h(s[nt][0] - mnew0, s[nt][1] - mnew0));
                pf[nt][1] = ex2h2(pack2h(s[nt][2] - mnew1, s[nt][3] - mnew1));
            }

#pragma unroll
            for (int nt = 0; nt < 8; nt++) {
                o[nt][0] *= corr0; o[nt][1] *= corr0;
                o[nt][2] *= corr1; o[nt][3] *= corr1;
            }
            osum[0] *= corr0; osum[1] *= corr0;
            osum[2] *= corr1; osum[3] *= corr1;
        }

        // ---- O += P @ Vhi ; lsum via ones-column MMA ----
        // One ldsm_x4_t per (kc, nt2) yields fragments for nt=2*nt2 (v0,v1)
        // and nt=2*nt2+1 (v2,v3).
#pragma unroll
        for (int kc = 0; kc < 4; kc++) {
            unsigned a[4] = { pf[2 * kc][0],     pf[2 * kc][1],
                              pf[2 * kc + 1][0], pf[2 * kc + 1][1] };
            mma_f16(osum, a, ONES_H2, ONES_H2);
#pragma unroll
            for (int nt2 = 0; nt2 < 4; nt2++) {
                unsigned v0, v1, v2, v3;
                ldsm_x4_t(v0, v1, v2, v3,
                          vst_ad + 2 * (kc * 16 * KST + nt2 * 16));
                mma_f16(o[2 * nt2],     a, v0, v1);
                mma_f16(o[2 * nt2 + 1], a, v2, v3);
            }
        }
    }

    // ---- epilogue: normalize, split (bf16 for O-proj), write ----
    float inv0 = 1.0f / osum[0];
    float inv1 = 1.0f / osum[2];
    int q0 = qbase + w * 16 + g;
    size_t base0 = ((size_t)b * SEQ + q0) * D_MODEL + h * DK;
    size_t base1 = base0 + 8 * (size_t)D_MODEL;
#pragma unroll
    for (int nt = 0; nt < 8; nt++) {
        unsigned hi, lo;
        split2(o[nt][0] * inv0, o[nt][1] * inv0, hi, lo);
        *(unsigned*)&g_Ohi[base0 + nt * 8 + t * 2] = hi;
        *(unsigned*)&g_Olo[base0 + nt * 8 + t * 2] = lo;
        split2(o[nt][2] * inv1, o[nt][3] * inv1, hi, lo);
        *(unsigned*)&g_Ohi[base1 + nt * 8 + t * 2] = hi;
        *(unsigned*)&g_Olo[base1 + nt * 8 + t * 2] = lo;
    }
}

// ---------------------------------------------------------------------------

extern "C" void kernel_launch(void* const* d_in, const int* in_sizes, int n_in,
                              void* d_out, int out_size)
{
    (void)in_sizes; (void)n_in; (void)out_size;
    const float* q    = (const float*)d_in[0];
    const float* k    = (const float*)d_in[1];
    const float* v    = (const float*)d_in[2];
    const int*   mask = (const int*)  d_in[3];
    const float* Wq   = (const float*)d_in[4];
    const float* bq   = (const float*)d_in[5];
    const float* Wk   = (const float*)d_in[6];
    const float* bk   = (const float*)d_in[7];
    const float* Wv   = (const float*)d_in[8];
    const float* bv   = (const float*)d_in[9];
    const float* Wo   = (const float*)d_in[10];
    const float* bo   = (const float*)d_in[11];
    float* out = (float*)d_out;

    float *Qh;
    uint16_t *Inhi, *Inlo, *Whi, *Wlo, *Khi, *Klo, *Vhi, *Ohi, *Olo;
    cudaGetSymbolAddress((void**)&Qh,   g_Qh);
    cudaGetSymbolAddress((void**)&Inhi, g_Inhi);
    cudaGetSymbolAddress((void**)&Inlo, g_Inlo);
    cudaGetSymbolAddress((void**)&Whi,  g_Whi);
    cudaGetSymbolAddress((void**)&Wlo,  g_Wlo);
    cudaGetSymbolAddress((void**)&Khi,  g_Khi);
    cudaGetSymbolAddress((void**)&Klo,  g_Klo);
    cudaGetSymbolAddress((void**)&Vhi,  g_Vhi);
    cudaGetSymbolAddress((void**)&Ohi,  g_Ohi);
    cudaGetSymbolAddress((void**)&Olo,  g_Olo);

    cudaFuncSetAttribute(attn_kernel,
                         cudaFuncAttributeMaxDynamicSharedMemorySize,
                         ATTN_SMEM);
    cudaFuncSetAttribute(proj_kernel,
                         cudaFuncAttributeMaxDynamicSharedMemorySize,
                         PROJ_SMEM);

    mask_bits_kernel<<<SEQ * NWORDS / 256, 256>>>(mask);
    split_in_kernel<<<dim3(IN_SZ / 1024, 3), 256>>>(q, k, v);
    split_w_kernel<<<dim3(W_SZ / 1024, 4), 256>>>(Wq, Wk, Wv, Wo);

    dim3 proj_grid(D_MODEL / PBN, MTOT / PBM);   // (8, 64)
    proj_kernel<<<proj_grid, 128, PROJ_SMEM>>>(
        Inhi, Inlo, Whi, Wlo, bq, Qh, nullptr, nullptr, 1);
    proj_kernel<<<proj_grid, 128, PROJ_SMEM>>>(
        Inhi + IN_SZ, Inlo + IN_SZ, Whi + W_SZ, Wlo + W_SZ,
        bk, nullptr, Khi, Klo, 2);
    proj_kernel<<<proj_grid, 128, PROJ_SMEM>>>(
        Inhi + 2 * IN_SZ, Inlo + 2 * IN_SZ, Whi + 2 * W_SZ, Wlo + 2 * W_SZ,
        bv, nullptr, Vhi, nullptr, 2);

    dim3 attn_grid(SEQ / 64, NH, BATCH);         // (32, 8, 4)
    attn_kernel<<<attn_grid, 128, ATTN_SMEM>>>();

    proj_kernel<<<proj_grid, 128, PROJ_SMEM>>>(
        Ohi, Olo, Whi + 3 * W_SZ, Wlo + 3 * W_SZ, bo, out, nullptr, nullptr, 0);
}

// round 17
// speedup vs baseline: 1.5052x; 1.2160x over previous
#include <cuda_runtime.h>
#include <cuda_bf16.h>
#include <math.h>
#include <stdint.h>

#define D_MODEL 512
#define NH      8
#define DK      64
#define BATCH   4
#define SEQ     2048
#define MTOT    (BATCH * SEQ)   // 8192
#define NWORDS  (SEQ / 32)      // 64 mask words per row
#define IN_SZ   ((size_t)MTOT * D_MODEL)     // 4194304
#define W_SZ    ((size_t)D_MODEL * D_MODEL)  // 262144

// Scratch (allocation-free rule: __device__ globals)
__device__ float g_Qh[IN_SZ];
__device__ __align__(16) uint16_t g_Inhi[3 * IN_SZ];
__device__ __align__(16) uint16_t g_Inlo[3 * IN_SZ];
__device__ __align__(16) uint16_t g_Whi[4 * W_SZ];
__device__ __align__(16) uint16_t g_Wlo[4 * W_SZ];
__device__ __align__(16) uint16_t g_Khi[IN_SZ];   // f16 (single term)
__device__ __align__(16) uint16_t g_Vhi[IN_SZ];   // f16 (single term)
__device__ __align__(16) uint16_t g_Ohi[IN_SZ];   // bf16 hi/lo (O-proj operand)
__device__ __align__(16) uint16_t g_Olo[IN_SZ];
__device__ __align__(16) unsigned g_Mb[(size_t)SEQ * NWORDS];

// ---------------------------------------------------------------------------
// bf16 helpers
// ---------------------------------------------------------------------------
__device__ __forceinline__ unsigned pack2(float e0, float e1) {
    unsigned r;
    asm("cvt.rn.bf16x2.f32 %0, %1, %2;" : "=r"(r) : "f"(e1), "f"(e0));
    return r;
}
__device__ __forceinline__ void split2(float x0, float x1,
                                       unsigned& hi, unsigned& lo) {
    hi = pack2(x0, x1);
    float h0 = __uint_as_float(hi << 16);
    float h1 = __uint_as_float(hi & 0xffff0000u);
    lo = pack2(x0 - h0, x1 - h1);
}

// ---------------------------------------------------------------------------
// f16 helpers
// ---------------------------------------------------------------------------
__device__ __forceinline__ unsigned pack2h(float e0, float e1) {
    unsigned r;
    asm("cvt.rn.f16x2.f32 %0, %1, %2;" : "=r"(r) : "f"(e1), "f"(e0));
    return r;
}
__device__ __forceinline__ void split2h(float x0, float x1,
                                        unsigned& hi, unsigned& lo) {
    hi = pack2h(x0, x1);
    float h0, h1;
    asm("{.reg .f16 a,b;\n\t mov.b32 {a,b}, %2;\n\t"
        "cvt.f32.f16 %0, a;\n\t cvt.f32.f16 %1, b;}"
        : "=f"(h0), "=f"(h1) : "r"(hi));
    lo = pack2h(x0 - h0, x1 - h1);
}
__device__ __forceinline__ unsigned ex2h2(unsigned d) {
    unsigned r;
    asm("ex2.approx.f16x2 %0, %1;" : "=r"(r) : "r"(d));
    return r;
}

// m16n8k16 MMAs, D += A*B
__device__ __forceinline__ void mma_bf16(float c[4], const unsigned a[4],
                                         unsigned b0, unsigned b1) {
    asm("mma.sync.aligned.m16n8k16.row.col.f32.bf16.bf16.f32 "
        "{%0,%1,%2,%3}, {%4,%5,%6,%7}, {%8,%9}, {%0,%1,%2,%3};"
        : "+f"(c[0]), "+f"(c[1]), "+f"(c[2]), "+f"(c[3])
        : "r"(a[0]), "r"(a[1]), "r"(a[2]), "r"(a[3]), "r"(b0), "r"(b1));
}
__device__ __forceinline__ void mma_f16(float c[4], const unsigned a[4],
                                        unsigned b0, unsigned b1) {
    asm("mma.sync.aligned.m16n8k16.row.col.f32.f16.f16.f32 "
        "{%0,%1,%2,%3}, {%4,%5,%6,%7}, {%8,%9}, {%0,%1,%2,%3};"
        : "+f"(c[0]), "+f"(c[1]), "+f"(c[2]), "+f"(c[3])
        : "r"(a[0]), "r"(a[1]), "r"(a[2]), "r"(a[3]), "r"(b0), "r"(b1));
}

__device__ __forceinline__ void ldsm_x4(unsigned& r0, unsigned& r1,
                                        unsigned& r2, unsigned& r3,
                                        unsigned addr) {
    asm volatile("ldmatrix.sync.aligned.m8n8.x4.shared.b16 {%0,%1,%2,%3}, [%4];"
                 : "=r"(r0), "=r"(r1), "=r"(r2), "=r"(r3) : "r"(addr));
}
__device__ __forceinline__ void ldsm_x4_t(unsigned& r0, unsigned& r1,
                                          unsigned& r2, unsigned& r3,
                                          unsigned addr) {
    asm volatile("ldmatrix.sync.aligned.m8n8.x4.trans.shared.b16 {%0,%1,%2,%3}, [%4];"
                 : "=r"(r0), "=r"(r1), "=r"(r2), "=r"(r3) : "r"(addr));
}

// cp.async helpers
__device__ __forceinline__ void cp16(unsigned saddr, const void* g) {
    asm volatile("cp.async.cg.shared.global [%0], [%1], 16;"
                 :: "r"(saddr), "l"(g));
}
__device__ __forceinline__ void cp8(unsigned saddr, const void* g) {
    asm volatile("cp.async.ca.shared.global [%0], [%1], 8;"
                 :: "r"(saddr), "l"(g));
}
__device__ __forceinline__ void cp_commit() {
    asm volatile("cp.async.commit_group;");
}
template<int N> __device__ __forceinline__ void cp_wait() {
    asm volatile("cp.async.wait_group %0;" :: "n"(N));
}

// ---------------------------------------------------------------------------
// Prep kernels
// ---------------------------------------------------------------------------
__global__ __launch_bounds__(256)
void mask_bits_kernel(const int* __restrict__ mask)
{
    int w = blockIdx.x * 256 + threadIdx.x;
    const int* mp = mask + (size_t)w * 32;
    unsigned bits = 0;
#pragma unroll
    for (int j = 0; j < 8; j++) {
        int4 m = *(const int4*)(mp + 4 * j);
        bits |= (unsigned)(m.x != 0) << (4 * j);
        bits |= (unsigned)(m.y != 0) << (4 * j + 1);
        bits |= (unsigned)(m.z != 0) << (4 * j + 2);
        bits |= (unsigned)(m.w != 0) << (4 * j + 3);
    }
    g_Mb[w] = bits;
}

__global__ __launch_bounds__(256)
void split_in_kernel(const float* __restrict__ q,
                     const float* __restrict__ k,
                     const float* __restrict__ v)
{
    int which = blockIdx.y;
    const float* src = (which == 0) ? q : (which == 1) ? k : v;
    size_t i = ((size_t)blockIdx.x * 256 + threadIdx.x) * 4;
    float4 x = *(const float4*)(src + i);
    unsigned h01, l01, h23, l23;
    split2(x.x, x.y, h01, l01);
    split2(x.z, x.w, h23, l23);
    size_t o = (size_t)which * IN_SZ + i;
    *(uint2*)&g_Inhi[o] = make_uint2(h01, h23);
    *(uint2*)&g_Inlo[o] = make_uint2(l01, l23);
}

__global__ __launch_bounds__(256)
void split_w_kernel(const float* __restrict__ w0,
                    const float* __restrict__ w1,
                    const float* __restrict__ w2,
                    const float* __restrict__ w3)
{
    int which = blockIdx.y;
    const float* src = (which == 0) ? w0 : (which == 1) ? w1
                     : (which == 2) ? w2 : w3;
    size_t i = ((size_t)blockIdx.x * 256 + threadIdx.x) * 4;
    float4 x = *(const float4*)(src + i);
    unsigned h01, l01, h23, l23;
    split2(x.x, x.y, h01, l01);
    split2(x.z, x.w, h23, l23);
    size_t o = (size_t)which * W_SZ + i;
    *(uint2*)&g_Whi[o] = make_uint2(h01, h23);
    *(uint2*)&g_Wlo[o] = make_uint2(l01, l23);
}

// ---------------------------------------------------------------------------
// Projection GEMM (unchanged R13/R16 config): 128 threads, 128x64x32, 4 warps.
// mode 0: f32 [M,512]; mode 1: f32 head layout; mode 2: f16 head layout
//   mode 2: Yhi = RN_f16(val); Ylo (if non-null) = f16(val - hi).
// ---------------------------------------------------------------------------
#define PBM  128
#define PBN  64
#define PBK  32
#define PKST 40
#define P_STG_U16   (2 * PBM * PKST + 2 * PBN * PKST)   // 15360
#define P_STG_BYTES (P_STG_U16 * 2)                      // 30720
#define PROJ_SMEM   (2 * P_STG_BYTES)                    // 61440
#define NKI  (D_MODEL / PBK)                             // 16

__device__ __forceinline__ void proj_stage(unsigned sb,
        const uint16_t* __restrict__ Ahi, const uint16_t* __restrict__ Alo,
        const uint16_t* __restrict__ Whi, const uint16_t* __restrict__ Wlo,
        int m0, int n0, int k0, int tid)
{
#pragma unroll
    for (int l = 0; l < 4; l++) {
        int v   = l * 128 + tid;
        int row = v >> 2, cb = v & 3;
        size_t   go = (size_t)(m0 + row) * D_MODEL + k0 + cb * 8;
        unsigned so = 2u * (row * PKST + cb * 8);
        cp16(sb + so,                     Ahi + go);
        cp16(sb + 2u * PBM * PKST + so,   Alo + go);
    }
#pragma unroll
    for (int l = 0; l < 2; l++) {
        int v   = l * 128 + tid;
        int row = v >> 2, cb = v & 3;
        size_t   go = (size_t)(n0 + row) * D_MODEL + k0 + cb * 8;
        unsigned so = 2u * (row * PKST + cb * 8);
        cp16(sb + 4u * PBM * PKST + so,                     Whi + go);
        cp16(sb + 4u * PBM * PKST + 2u * PBN * PKST + so,   Wlo + go);
    }
    cp_commit();
}

__global__ __launch_bounds__(128)
void proj_kernel(const uint16_t* __restrict__ Ahi,
                 const uint16_t* __restrict__ Alo,
                 const uint16_t* __restrict__ Whi,
                 const uint16_t* __restrict__ Wlo,
                 const float* __restrict__ bias,
                 float* __restrict__ Yf,
                 uint16_t* __restrict__ Yhi,
                 uint16_t* __restrict__ Ylo,
                 int mode)
{
    extern __shared__ char psm[];
    const unsigned sbase = (unsigned)__cvta_generic_to_shared(psm);

    const int tid  = threadIdx.x;
    const int lane = tid & 31;
    const int w    = tid >> 5;
    const int wm   = w & 1;
    const int wn   = w >> 1;
    const int g    = lane >> 2;
    const int t    = lane & 3;
    const int m0   = blockIdx.y * PBM;
    const int n0   = blockIdx.x * PBN;

    float c[4][4][4];
#pragma unroll
    for (int i = 0; i < 4; i++)
#pragma unroll
        for (int j = 0; j < 4; j++)
#pragma unroll
            for (int q = 0; q < 4; q++) c[i][j][q] = 0.f;

    const unsigned a_lane = (wm * 64 + ((lane >> 3) & 1) * 8 + (lane & 7)) * PKST
                          + (lane >> 4) * 8;
    const unsigned b_lane = (wn * 32 + (lane & 7)) * PKST
                          + ((lane >> 3) & 1) * 8
                          + (lane >> 4) * (PBN * PKST);
    const unsigned a_hi_off = 2 * a_lane;
    const unsigned a_lo_off = a_hi_off + 2 * (PBM * PKST);
    const unsigned b_off    = 4 * PBM * PKST + 2 * b_lane;

    proj_stage(sbase, Ahi, Alo, Whi, Wlo, m0, n0, 0, tid);

    for (int ki = 0; ki < NKI; ki++) {
        const int st = ki & 1;
        __syncthreads();
        if (ki + 1 < NKI) {
            proj_stage(sbase + (st ^ 1) * P_STG_BYTES,
                       Ahi, Alo, Whi, Wlo, m0, n0, (ki + 1) * PBK, tid);
            cp_wait<1>();
        } else {
            cp_wait<0>();
        }
        __syncthreads();

        const unsigned sb = sbase + st * P_STG_BYTES;
#pragma unroll
        for (int kk = 0; kk < 2; kk++) {
            unsigned ah[4][4], al[4][4];
#pragma unroll
            for (int mt = 0; mt < 4; mt++) {
                unsigned off = 2 * (mt * 16 * PKST + kk * 16);
                ldsm_x4(ah[mt][0], ah[mt][1], ah[mt][2], ah[mt][3],
                        sb + a_hi_off + off);
                ldsm_x4(al[mt][0], al[mt][1], al[mt][2], al[mt][3],
                        sb + a_lo_off + off);
            }
#pragma unroll
            for (int nt = 0; nt < 4; nt++) {
                unsigned bh0, bh1, bl0, bl1;
                ldsm_x4(bh0, bh1, bl0, bl1,
                        sb + b_off + 2 * (nt * 8 * PKST + kk * 16));
#pragma unroll
                for (int mt = 0; mt < 4; mt++) {
                    mma_bf16(c[mt][nt], al[mt], bh0, bh1);
                    mma_bf16(c[mt][nt], ah[mt], bl0, bl1);
                    mma_bf16(c[mt][nt], ah[mt], bh0, bh1);
                }
            }
        }
    }

    // ---- epilogue ----
#pragma unroll
    for (int mt = 0; mt < 4; mt++) {
#pragma unroll
        for (int nt = 0; nt < 4; nt++) {
            int n = n0 + wn * 32 + nt * 8 + t * 2;
            float2 bi = *(const float2*)(bias + n);
#pragma unroll
            for (int half = 0; half < 2; half++) {
                int m = m0 + wm * 64 + mt * 16 + g + half * 8;
                float2 val = make_float2(c[mt][nt][half * 2]     + bi.x,
                                         c[mt][nt][half * 2 + 1] + bi.y);
                if (mode == 0) {
                    *(float2*)&Yf[(size_t)m * D_MODEL + n] = val;
                } else {
                    int bb = m >> 11;
                    int s  = m & (SEQ - 1);
                    int hh = n >> 6;
                    int d  = n & (DK - 1);
                    size_t idx = (((size_t)(bb * NH + hh) * SEQ) + s) * DK + d;
                    if (mode == 1) {
                        *(float2*)&Yf[idx] = val;
                    } else {
                        unsigned hi, lo;
                        split2h(val.x, val.y, hi, lo);
                        *(unsigned*)&Yhi[idx] = hi;
                        if (Ylo) *(unsigned*)&Ylo[idx] = lo;
                    }
                }
            }
        }
    }
}

// ---------------------------------------------------------------------------
// Flash attention (128 thr, BQ=64): QK single-term f16 (double-block ldsm:
// lanes 16-31 read the next 8-key block, one ldsm_x4 feeds two nt's);
// softmax via ex2.approx.f16x2; PV single-term f16 (double-block trans ldsm);
// lsum via ones-column MMA. Staging: Khi | Vhi only.
// ---------------------------------------------------------------------------
#define BKT   64
#define NT_T  (SEQ / BKT)          // 32 tiles
#define KST   72
#define MAT_U16   (64 * KST)       // 4608
#define MAT_BYTES (MAT_U16 * 2)    // 9216
#define STG_BYTES (2 * MAT_BYTES)  // 18432
#define MS_OFF_BYTES (2 * STG_BYTES)
#define ATTN_SMEM (MS_OFF_BYTES + 2 * 128 * 4)   // 37888
#define ONES_H2  0x3C003C00u       // f16x2 {1.0, 1.0}
#define SC2      0.18033688f       // 0.125 * log2(e)

__device__ __forceinline__ void stage_tile(unsigned smem_u32, int st,
                                           size_t bh, int qbase, int tile,
                                           int tid)
{
    const int k0 = tile * BKT;
    const unsigned sb = smem_u32 + st * STG_BYTES;
#pragma unroll
    for (int l = 0; l < 4; l++) {
        int cc  = tid + l * 128;
        int row = cc >> 3;
        int col = cc & 7;
        size_t  go = (size_t)(bh + k0 + row) * DK + col * 8;
        unsigned so = 2 * (row * KST + col * 8);
        cp16(sb + so,             g_Khi + go);
        cp16(sb + MAT_BYTES + so, g_Vhi + go);
    }
    if (tid < 64) {
        cp8(smem_u32 + MS_OFF_BYTES + st * 512 + tid * 8,
            g_Mb + (size_t)(qbase + tid) * NWORDS + tile * 2);
    }
    cp_commit();
}

__global__ __launch_bounds__(128)
void attn_kernel()
{
    extern __shared__ char dsm[];
    const unsigned smem_u32 = (unsigned)__cvta_generic_to_shared(dsm);
    const unsigned* Msp = (const unsigned*)(dsm + MS_OFF_BYTES);

    const int tid  = threadIdx.x;
    const int w    = tid >> 5;
    const int lane = tid & 31;
    const int g    = lane >> 2;
    const int t    = lane & 3;
    const int b    = blockIdx.z;
    const int h    = blockIdx.y;
    const int qbase = blockIdx.x * 64;
    const size_t bh = ((size_t)b * NH + h) * SEQ;

    stage_tile(smem_u32, 0, bh, qbase, 0, tid);

    // ---- Q fragments (plain f16) once ----
    unsigned ah[4][4];
    {
        const float* q0p = g_Qh + (bh + qbase + w * 16 + g) * DK;
        const float* q1p = q0p + 8 * DK;
#pragma unroll
        for (int kc = 0; kc < 4; kc++) {
            int d = kc * 16 + t * 2;
            ah[kc][0] = pack2h(q0p[d],     q0p[d + 1]);
            ah[kc][1] = pack2h(q1p[d],     q1p[d + 1]);
            ah[kc][2] = pack2h(q0p[d + 8], q0p[d + 9]);
            ah[kc][3] = pack2h(q1p[d + 8], q1p[d + 9]);
        }
    }

    float o[8][4];
#pragma unroll
    for (int nt = 0; nt < 8; nt++)
#pragma unroll
        for (int i = 0; i < 4; i++) o[nt][i] = 0.f;
    float osum[4] = {0.f, 0.f, 0.f, 0.f};
    float mrow0 = -1e30f, mrow1 = -1e30f;

    // K (non-trans x4, two 8-key blocks per load): lanes 0-15 keys 0-7
    // (d, d+8); lanes 16-31 keys +8.
    const unsigned k_lane = ((lane & 7) + (lane >> 4) * 8) * KST
                          + ((lane >> 3) & 1) * 8;
    // V (trans x4, two 8-col blocks per load): lanes 16-31 at +8 cols.
    const unsigned v_lane = ((lane & 7) + ((lane >> 3) & 1) * 8) * KST
                          + (lane >> 4) * 8;
    const unsigned k_ad = smem_u32 + 2 * k_lane;
    const unsigned v_ad = smem_u32 + MAT_BYTES + 2 * v_lane;

    for (int tile = 0; tile < NT_T; tile++) {
        const int st = tile & 1;
        __syncthreads();
        if (tile + 1 < NT_T) {
            stage_tile(smem_u32, st ^ 1, bh, qbase, tile + 1, tid);
            cp_wait<1>();
        } else {
            cp_wait<0>();
        }
        __syncthreads();

        const unsigned kst_ad = k_ad + st * STG_BYTES;
        const unsigned vst_ad = v_ad + st * STG_BYTES;

        // ---- S = Q @ K^T (single-term f16, double-block ldsm) ----
        float s[8][4];
#pragma unroll
        for (int nt2 = 0; nt2 < 4; nt2++) {
            float c0[4] = {0.f, 0.f, 0.f, 0.f};
            float c1[4] = {0.f, 0.f, 0.f, 0.f};
#pragma unroll
            for (int kc = 0; kc < 4; kc++) {
                unsigned b0, b1, b2, b3;
                ldsm_x4(b0, b1, b2, b3,
                        kst_ad + 2 * (nt2 * 16 * KST + kc * 16));
                mma_f16(c0, ah[kc], b0, b1);
                mma_f16(c1, ah[kc], b2, b3);
            }
#pragma unroll
            for (int i = 0; i < 4; i++) {
                s[2 * nt2][i]     = c0[i];
                s[2 * nt2 + 1][i] = c1[i];
            }
        }

        // ---- mask + scale (log2 domain) + online softmax ----
        unsigned pf[8][2];
        {
            int row0 = w * 16 + g;
            const unsigned* ms = Msp + st * 128;
            unsigned long long M0 = (unsigned long long)ms[row0 * 2]
                                  | ((unsigned long long)ms[row0 * 2 + 1] << 32);
            unsigned long long M1 = (unsigned long long)ms[(row0 + 8) * 2]
                                  | ((unsigned long long)ms[(row0 + 8) * 2 + 1] << 32);
            float rmax0 = -1e30f, rmax1 = -1e30f;
#pragma unroll
            for (int nt = 0; nt < 8; nt++) {
                unsigned sh = nt * 8 + t * 2;
                unsigned b0 = (unsigned)(M0 >> sh);
                unsigned b1 = (unsigned)(M1 >> sh);
                s[nt][0] = (b0 & 1u) ? s[nt][0] * SC2 : -1e9f;
                s[nt][1] = (b0 & 2u) ? s[nt][1] * SC2 : -1e9f;
                s[nt][2] = (b1 & 1u) ? s[nt][2] * SC2 : -1e9f;
                s[nt][3] = (b1 & 2u) ? s[nt][3] * SC2 : -1e9f;
                rmax0 = fmaxf(rmax0, fmaxf(s[nt][0], s[nt][1]));
                rmax1 = fmaxf(rmax1, fmaxf(s[nt][2], s[nt][3]));
            }
            rmax0 = fmaxf(rmax0, __shfl_xor_sync(0xffffffffu, rmax0, 1));
            rmax0 = fmaxf(rmax0, __shfl_xor_sync(0xffffffffu, rmax0, 2));
            rmax1 = fmaxf(rmax1, __shfl_xor_sync(0xffffffffu, rmax1, 1));
            rmax1 = fmaxf(rmax1, __shfl_xor_sync(0xffffffffu, rmax1, 2));

            float mnew0 = fmaxf(mrow0, rmax0);
            float mnew1 = fmaxf(mrow1, rmax1);
            float corr0 = exp2f(mrow0 - mnew0);
            float corr1 = exp2f(mrow1 - mnew1);
            mrow0 = mnew0; mrow1 = mnew1;

#pragma unroll
            for (int nt = 0; nt < 8; nt++) {
                pf[nt][0] = ex2h2(pack2h(s[nt][0] - mnew0, s[nt][1] - mnew0));
                pf[nt][1] = ex2h2(pack2h(s[nt][2] - mnew1, s[nt][3] - mnew1));
            }

#pragma unroll
            for (int nt = 0; nt < 8; nt++) {
                o[nt][0] *= corr0; o[nt][1] *= corr0;
                o[nt][2] *= corr1; o[nt][3] *= corr1;
            }
            osum[0] *= corr0; osum[1] *= corr0;
            osum[2] *= corr1; osum[3] *= corr1;
        }

        // ---- O += P @ Vhi ; lsum via ones-column MMA ----
#pragma unroll
        for (int kc = 0; kc < 4; kc++) {
            unsigned a[4] = { pf[2 * kc][0],     pf[2 * kc][1],
                              pf[2 * kc + 1][0], pf[2 * kc + 1][1] };
            mma_f16(osum, a, ONES_H2, ONES_H2);
#pragma unroll
            for (int nt2 = 0; nt2 < 4; nt2++) {
                unsigned v0, v1, v2, v3;
                ldsm_x4_t(v0, v1, v2, v3,
                          vst_ad + 2 * (kc * 16 * KST + nt2 * 16));
                mma_f16(o[2 * nt2],     a, v0, v1);
                mma_f16(o[2 * nt2 + 1], a, v2, v3);
            }
        }
    }

    // ---- epilogue: normalize, split (bf16 for O-proj), write ----
    float inv0 = 1.0f / osum[0];
    float inv1 = 1.0f / osum[2];
    int q0 = qbase + w * 16 + g;
    size_t base0 = ((size_t)b * SEQ + q0) * D_MODEL + h * DK;
    size_t base1 = base0 + 8 * (size_t)D_MODEL;
#pragma unroll
    for (int nt = 0; nt < 8; nt++) {
        unsigned hi, lo;
        split2(o[nt][0] * inv0, o[nt][1] * inv0, hi, lo);
        *(unsigned*)&g_Ohi[base0 + nt * 8 + t * 2] = hi;
        *(unsigned*)&g_Olo[base0 + nt * 8 + t * 2] = lo;
        split2(o[nt][2] * inv1, o[nt][3] * inv1, hi, lo);
        *(unsigned*)&g_Ohi[base1 + nt * 8 + t * 2] = hi;
        *(unsigned*)&g_Olo[base1 + nt * 8 + t * 2] = lo;
    }
}

// ---------------------------------------------------------------------------

extern "C" void kernel_launch(void* const* d_in, const int* in_sizes, int n_in,
                              void* d_out, int out_size)
{
    (void)in_sizes; (void)n_in; (void)out_size;
    const float* q    = (const float*)d_in[0];
    const float* k    = (const float*)d_in[1];
    const float* v    = (const float*)d_in[2];
    const int*   mask = (const int*)  d_in[3];
    const float* Wq   = (const float*)d_in[4];
    const float* bq   = (const float*)d_in[5];
    const float* Wk   = (const float*)d_in[6];
    const float* bk   = (const float*)d_in[7];
    const float* Wv   = (const float*)d_in[8];
    const float* bv   = (const float*)d_in[9];
    const float* Wo   = (const float*)d_in[10];
    const float* bo   = (const float*)d_in[11];
    float* out = (float*)d_out;

    float *Qh;
    uint16_t *Inhi, *Inlo, *Whi, *Wlo, *Khi, *Vhi, *Ohi, *Olo;
    cudaGetSymbolAddress((void**)&Qh,   g_Qh);
    cudaGetSymbolAddress((void**)&Inhi, g_Inhi);
    cudaGetSymbolAddress((void**)&Inlo, g_Inlo);
    cudaGetSymbolAddress((void**)&Whi,  g_Whi);
    cudaGetSymbolAddress((void**)&Wlo,  g_Wlo);
    cudaGetSymbolAddress((void**)&Khi,  g_Khi);
    cudaGetSymbolAddress((void**)&Vhi,  g_Vhi);
    cudaGetSymbolAddress((void**)&Ohi,  g_Ohi);
    cudaGetSymbolAddress((void**)&Olo,  g_Olo);

    cudaFuncSetAttribute(attn_kernel,
                         cudaFuncAttributeMaxDynamicSharedMemorySize,
                         ATTN_SMEM);
    cudaFuncSetAttribute(proj_kernel,
                         cudaFuncAttributeMaxDynamicSharedMemorySize,
                         PROJ_SMEM);

    mask_bits_kernel<<<SEQ * NWORDS / 256, 256>>>(mask);
    split_in_kernel<<<dim3(IN_SZ / 1024, 3), 256>>>(q, k, v);
    split_w_kernel<<<dim3(W_SZ / 1024, 4), 256>>>(Wq, Wk, Wv, Wo);

    dim3 proj_grid(D_MODEL / PBN, MTOT / PBM);   // (8, 64)
    proj_kernel<<<proj_grid, 128, PROJ_SMEM>>>(
        Inhi, Inlo, Whi, Wlo, bq, Qh, nullptr, nullptr, 1);
    proj_kernel<<<proj_grid, 128, PROJ_SMEM>>>(
        Inhi + IN_SZ, Inlo + IN_SZ, Whi + W_SZ, Wlo + W_SZ,
        bk, nullptr, Khi, nullptr, 2);
    proj_kernel<<<proj_grid, 128, PROJ_SMEM>>>(
        Inhi + 2 * IN_SZ, Inlo + 2 * IN_SZ, Whi + 2 * W_SZ, Wlo + 2 * W_SZ,
        bv, nullptr, Vhi, nullptr, 2);

    dim3 attn_grid(SEQ / 64, NH, BATCH);         // (32, 8, 4)
    attn_kernel<<<attn_grid, 128, ATTN_SMEM>>>();

    proj_kernel<<<proj_grid, 128, PROJ_SMEM>>>(
        Ohi, Olo, Whi + 3 * W_SZ, Wlo + 3 * W_SZ, bo, out, nullptr, nullptr, 0);
}